// round 6
// baseline (speedup 1.0000x reference)
#include <cuda_runtime.h>
#include <cstdint>

// ---------------------------------------------------------------------------
// LocationSensitiveAttention — barrier-free multi-kernel CUDA-graph design.
// B=32, T_ENC=1024, T_DEC=512, E=U=512, FILTERS=32, KERNEL=31.
//
// 514 launches per call:
//   k_weff                : fold conv_w @ w_loc -> Weff[31,512] (f32x2 packed)
//   kA(t), t=0..511       : finalize step t-1 (e, prev) + compute step t
//                           (loc Toeplitz GEMM + tanh + v_a reduce + exp)
//   kE                    : finalize e(511)
//   kC                    : c = e_out @ enc  (batched GEMM, overwrites c)
// All cross-step / cross-CTA ordering comes from kernel-launch edges.
// State (prev, exs, psum) is double-buffered so a launch never reads a
// location another CTA writes in the same launch.
// ---------------------------------------------------------------------------

#define BQ 32
#define TENC 1024
#define TDEC 512
#define EDIM 512
#define NFILT 32
#define KW 31
#define NUP 256              // u-pairs (EDIM/2)

typedef unsigned long long ull;

// static device scratch (no allocation)
__device__ ull   g_W2[KW * NUP];          // Weff packed f32x2 [k][upair]
__device__ ull   g_cb2[NUP];              // conv_b @ w_loc packed
__device__ float g_prevb[2][BQ * TENC];   // double-buffered cumulative align
__device__ float g_exs[2][BQ * TENC];     // double-buffered exp(e_raw)
__device__ float g_psum[2][BQ * 4];       // double-buffered per-slice sums

// ---- f32x2 helpers --------------------------------------------------------
__device__ __forceinline__ ull fma2(ull a, ull b, ull c) {
    ull d;
    asm("fma.rn.f32x2 %0, %1, %2, %3;" : "=l"(d) : "l"(a), "l"(b), "l"(c));
    return d;
}
__device__ __forceinline__ ull add2(ull a, ull b) {
    ull d;
    asm("add.rn.f32x2 %0, %1, %2;" : "=l"(d) : "l"(a), "l"(b));
    return d;
}
__device__ __forceinline__ ull pack2(float lo, float hi) {
    ull d;
    asm("mov.b64 %0, {%1, %2};" : "=l"(d) : "f"(lo), "f"(hi));
    return d;
}
__device__ __forceinline__ void unpack2(ull v, float& lo, float& hi) {
    asm("mov.b64 {%0, %1}, %2;" : "=f"(lo), "=f"(hi) : "l"(v));
}
// tanh(x) = 1 - 2/(1+exp(2x)); ex2+rcp approx (~1e-6), saturates correctly.
__device__ __forceinline__ float fast_tanh(float x) {
    float m = x * 2.8853900817779268f;    // 2*log2(e)
    float t, r;
    asm("ex2.approx.f32 %0, %1;" : "=f"(t) : "f"(m));
    float d = 1.0f + t;
    asm("rcp.approx.f32 %0, %1;" : "=f"(r) : "f"(d));
    return fmaf(-2.0f, r, 1.0f);
}

// ---- weight folding -------------------------------------------------------
__global__ void k_weff(const float* __restrict__ cw, const float* __restrict__ cb,
                       const float* __restrict__ wl) {
    int idx = blockIdx.x * blockDim.x + threadIdx.x;
    if (idx < KW * NUP) {
        int k = idx / NUP, up = idx % NUP;
        float slo = 0.0f, shi = 0.0f;
        #pragma unroll
        for (int f = 0; f < NFILT; ++f) {
            float w = cw[k * NFILT + f];
            slo += w * wl[f * EDIM + 2 * up];
            shi += w * wl[f * EDIM + 2 * up + 1];
        }
        g_W2[idx] = pack2(slo, shi);
    }
    if (idx < NUP) {
        float slo = 0.0f, shi = 0.0f;
        #pragma unroll
        for (int f = 0; f < NFILT; ++f) {
            float w = cb[f];
            slo += w * wl[f * EDIM + 2 * idx];
            shi += w * wl[f * EDIM + 2 * idx + 1];
        }
        g_cb2[idx] = pack2(slo, shi);
    }
}

// ---- per-step kernel ------------------------------------------------------
// CTA (b, slice): b = bx>>2, slice = bx&3; owns te in [slice*256, slice*256+256).
// Buffers: kA(t) reads prevb[t&1] (= prev(t-2)) and exs/psum[(t+1)&1] (= step
// t-1); writes prevb[(t+1)&1] (= prev(t-1)) and exs/psum[t&1] (= step t).
__global__ void __launch_bounds__(512)
kA(int t, const float* __restrict__ enc, const float* __restrict__ dec,
   const float* __restrict__ va, const float* __restrict__ ba,
   float* __restrict__ out) {
    const int bx = blockIdx.x;
    const int b = bx >> 2;
    const int slice = bx & 3;
    const int te0 = slice * 256;

    const int tid = threadIdx.x;
    const int lane = tid & 31;
    const int warp = tid >> 5;
    const int wu = warp & 7;            // u-group
    const int half = warp >> 3;         // te half (0..1)
    const int upair = wu * 32 + lane;   // 0..255

    __shared__ ull p2s[288];            // dup-packed prev(t-1) window
    __shared__ float part_s[8][256];
    __shared__ float red_s[16];

    const ull* enc2 = reinterpret_cast<const ull*>(enc);
    const ull* dec2 = reinterpret_cast<const ull*>(dec);
    const ull* va2  = reinterpret_cast<const ull*>(va);
    const ull* ba2  = reinterpret_cast<const ull*>(ba);
    float* e_out = out + (size_t)BQ * TDEC * EDIM;

    const int rdE = (t + 1) & 1;        // exs/psum buffer of step t-1
    const int wrE = t & 1;

    float inv = 0.0f;
    if (t > 0) {
        const float* ps = &g_psum[rdE][b * 4];
        inv = 1.0f / (ps[0] + ps[1] + ps[2] + ps[3]);
    }

    // finalize step t-1 (e, prev) + stage conv window
    if (tid < 286) {
        int te_g = te0 - 15 + tid;
        float pv = 0.0f, e = 0.0f;
        if (te_g >= 0 && te_g < TENC && t > 0) {
            pv = g_prevb[t & 1][b * TENC + te_g];
            e = g_exs[rdE][b * TENC + te_g] * inv;
            pv += e;
        }
        p2s[tid] = pack2(pv, pv);
        if (tid >= 15 && tid < 271) {   // own range
            g_prevb[(t + 1) & 1][b * TENC + te_g] = pv;
            if (t > 0)
                e_out[((size_t)b * TDEC + (t - 1)) * TENC + te_g] = e;
        }
    }

    float va_lo, va_hi;
    unpack2(__ldg(va2 + upair), va_lo, va_hi);
    ull qb2 = add2(add2(__ldg(dec2 + ((size_t)b * TDEC + t) * NUP + upair),
                        __ldg(ba2 + upair)),
                   g_cb2[upair]);
    __syncthreads();

    // loc (Toeplitz, f32x2) + tanh + v_a reduce
    for (int tile = 0; tile < 16; ++tile) {
        const int te_l = half * 128 + tile * 8;

        ull r[8], acc[8];
        #pragma unroll
        for (int j = 0; j < 8; ++j) { r[j] = p2s[te_l + j]; acc[j] = 0ull; }
        #pragma unroll
        for (int k = 0; k < KW; ++k) {
            ull wk = __ldg(&g_W2[k * NUP + upair]);
            #pragma unroll
            for (int j = 0; j < 8; ++j)
                acc[j] = fma2(r[(k + j) & 7], wk, acc[j]);
            if (k < KW - 1) r[k & 7] = p2s[te_l + k + 8];
        }

        float pj[8];
        #pragma unroll
        for (int j = 0; j < 8; ++j) {
            ull ev = __ldg(enc2 + ((size_t)b * TENC + te0 + te_l + j) * NUP + upair);
            ull arg = add2(add2(acc[j], ev), qb2);
            float xlo, xhi;
            unpack2(arg, xlo, xhi);
            pj[j] = fmaf(va_hi, fast_tanh(xhi), va_lo * fast_tanh(xlo));
        }
        #pragma unroll
        for (int j = 0; j < 8; ++j) {
            #pragma unroll
            for (int m = 16; m >= 1; m >>= 1)
                pj[j] += __shfl_xor_sync(0xffffffffu, pj[j], m);
        }
        if (lane == 0) {
            #pragma unroll
            for (int j = 0; j < 8; ++j) part_s[wu][te_l + j] = pj[j];
        }
    }
    __syncthreads();

    // exp + slice sum (no max-sub: |e_raw| <= sum|v_a| < 26, exp can't overflow)
    float ex = 0.0f;
    if (tid < 256) {
        float s = part_s[0][tid] + part_s[1][tid] + part_s[2][tid] +
                  part_s[3][tid] + part_s[4][tid] + part_s[5][tid] +
                  part_s[6][tid] + part_s[7][tid];
        ex = __expf(s);
        g_exs[wrE][b * TENC + te0 + tid] = ex;
    }
    float sw = ex;
    #pragma unroll
    for (int m = 16; m >= 1; m >>= 1)
        sw += __shfl_xor_sync(0xffffffffu, sw, m);
    if (lane == 0) red_s[warp] = sw;
    __syncthreads();
    if (tid == 0) {
        float tot = 0.0f;
        #pragma unroll
        for (int w = 0; w < 16; ++w) tot += red_s[w];
        g_psum[wrE][b * 4 + slice] = tot;
    }
}

// ---- finalize e(511) ------------------------------------------------------
__global__ void kE(float* __restrict__ out) {
    const int bx = blockIdx.x;
    const int b = bx >> 2;
    const int slice = bx & 3;
    const int tid = threadIdx.x;
    float* e_out = out + (size_t)BQ * TDEC * EDIM;
    const float* ps = &g_psum[1][b * 4];            // 511 & 1 == 1
    float inv = 1.0f / (ps[0] + ps[1] + ps[2] + ps[3]);
    int te = slice * 256 + tid;
    e_out[((size_t)b * TDEC + 511) * TENC + te] = g_exs[1][b * TENC + te] * inv;
}

// ---- final context GEMM: c[b,d,:] = sum_te e[b,d,te] * enc[b,te,:] --------
__global__ void __launch_bounds__(512)
kC(const float* __restrict__ enc, float* __restrict__ out) {
    const int dtile = blockIdx.x;     // 16 tiles of 32 d-rows
    const int b = blockIdx.y;
    const int tid = threadIdx.x;
    const int upair = tid & 255;
    const int dhalf = tid >> 8;       // 0..1 -> 16 d-rows each

    const ull* enc2 = reinterpret_cast<const ull*>(enc);
    const float* e_out = out + (size_t)BQ * TDEC * EDIM;

    __shared__ float es[32][128];
    ull acc[16];
    #pragma unroll
    for (int j = 0; j < 16; ++j) acc[j] = 0ull;

    for (int c = 0; c < 8; ++c) {     // te chunks of 128
        __syncthreads();
        for (int q = tid; q < 1024; q += 512) {   // 32 rows x 32 float4
            int row = q >> 5, col4 = q & 31;
            float4 v = __ldg((const float4*)
                &e_out[((size_t)b * TDEC + dtile * 32 + row) * TENC + c * 128 + col4 * 4]);
            *(float4*)&es[row][col4 * 4] = v;
        }
        __syncthreads();

        for (int te = 0; te < 128; te += 4) {
            ull ev0 = __ldg(&enc2[((size_t)b * TENC + c * 128 + te + 0) * NUP + upair]);
            ull ev1 = __ldg(&enc2[((size_t)b * TENC + c * 128 + te + 1) * NUP + upair]);
            ull ev2 = __ldg(&enc2[((size_t)b * TENC + c * 128 + te + 2) * NUP + upair]);
            ull ev3 = __ldg(&enc2[((size_t)b * TENC + c * 128 + te + 3) * NUP + upair]);
            #pragma unroll
            for (int j = 0; j < 16; ++j) {
                float4 e4 = *(const float4*)&es[dhalf * 16 + j][te];
                acc[j] = fma2(pack2(e4.x, e4.x), ev0, acc[j]);
                acc[j] = fma2(pack2(e4.y, e4.y), ev1, acc[j]);
                acc[j] = fma2(pack2(e4.z, e4.z), ev2, acc[j]);
                acc[j] = fma2(pack2(e4.w, e4.w), ev3, acc[j]);
            }
        }
    }

    #pragma unroll
    for (int j = 0; j < 16; ++j) {
        int d = dtile * 32 + dhalf * 16 + j;
        *(ull*)&out[((size_t)b * TDEC + d) * EDIM + 2 * upair] = acc[j];
    }
}

extern "C" void kernel_launch(void* const* d_in, const int* in_sizes, int n_in,
                              void* d_out, int out_size) {
    (void)in_sizes; (void)n_in; (void)out_size;
    const float* enc = (const float*)d_in[0];
    const float* dec = (const float*)d_in[1];
    const float* cw  = (const float*)d_in[2];
    const float* cb  = (const float*)d_in[3];
    const float* wl  = (const float*)d_in[4];
    const float* va  = (const float*)d_in[5];
    const float* ba  = (const float*)d_in[6];
    float* out = (float*)d_out;

    k_weff<<<32, 256>>>(cw, cb, wl);
    for (int t = 0; t < TDEC; ++t)
        kA<<<BQ * 4, 512>>>(t, enc, dec, va, ba, out);
    kE<<<BQ * 4, 256>>>(out);
    dim3 gc(16, BQ);
    kC<<<gc, 512>>>(enc, out);
}